// round 13
// baseline (speedup 1.0000x reference)
#include <cuda_runtime.h>

// axon_layer: dual-exponential PSP scan.
//   m_t = m_{t-1}*dm + x_t ; s_t = s_{t-1}*ds + x_t ; psp_t = (m_t - s_t)*v0
//
// Continuous 4-stage cp.async ring: each block owns 4 consecutive 64-row
// units (256 rows) and streams all 40 chunks through one ring with NO
// per-unit pipeline drain (refills cross unit boundaries). Grid = 512
// uniform blocks < capacity (740 @ 45KB smem) -> single wave, ~100%
// scheduling utilization. Register state (m,s,dm,ds) resets at unit
// boundaries; the memory stream never stops. Bit-exact scan.
//
// Inputs: [0] input_spikes f32 [B,F,T]  [1] decay_m f32 [F]
//         [2] decay_s f32 [F]           [3] v_0 f32 scalar
// Output: psps [B,F,T] then m_T [B,F] then s_T [B,F].

#define AX_THREADS 64
#define AX_ROWS    64            // rows per unit
#define AX_UNITS   4             // units per block (256 rows/block)
#define AX_T       400
#define AX_CH4     10            // float4 per chunk (160 B/row)
#define AX_STRIDE  11            // padded smem row stride (odd -> no LDS conflicts)
#define AX_NCHUNK  10            // chunks per unit
#define AX_GCHUNK  (AX_UNITS * AX_NCHUNK)   // 40 chunks per block
#define AX_NSTAGE  4
#define AX_RQ      (AX_T / 4)    // 100 float4 per row
#define AX_STAGEQ  (AX_ROWS * AX_STRIDE)    // 704 quads = 11264 B per stage

__device__ __forceinline__ void ax_cp_async16(void* smem_dst, const void* gmem_src) {
    unsigned saddr = (unsigned)__cvta_generic_to_shared(smem_dst);
    asm volatile("cp.async.cg.shared.global [%0], [%1], 16;\n"
                 :: "r"(saddr), "l"(gmem_src));
}
__device__ __forceinline__ void ax_cp_commit() {
    asm volatile("cp.async.commit_group;\n");
}
template <int N>
__device__ __forceinline__ void ax_cp_wait() {
    asm volatile("cp.async.wait_group %0;\n" :: "n"(N));
}

extern __shared__ float4 ax_smem[];   // AX_NSTAGE * AX_STAGEQ float4 = 45056 B

// Stage global-chunk g (unit = g/10, local chunk = g%10) into a ring stage.
// gbase = first quad of this block's 256-row region.
__device__ __forceinline__ void ax_issue_chunk(const float4* __restrict__ gbase,
                                               float4* __restrict__ stg,
                                               int g, int tid)
{
    const int u  = g / AX_NCHUNK;
    const int ch = g - u * AX_NCHUNK;
    const float4* gin = gbase + (long long)u * AX_ROWS * AX_RQ;
#pragma unroll
    for (int i = 0; i < AX_CH4; ++i) {
        int idx = i * AX_THREADS + tid;          // 0..639 linear over tile
        int r = idx / AX_CH4;
        int c = idx - r * AX_CH4;
        ax_cp_async16(&stg[r * AX_STRIDE + c],
                      &gin[(long long)r * AX_RQ + ch * AX_CH4 + c]);
    }
}

__global__ void __launch_bounds__(AX_THREADS)
axon_cring_kernel(const float* __restrict__ x,
                  const float* __restrict__ decay_m,
                  const float* __restrict__ decay_s,
                  const float* __restrict__ v0p,
                  float* __restrict__ out,
                  int F, long long n_rows)
{
    const int tid = threadIdx.x;
    const long long brow0 = (long long)blockIdx.x * (AX_UNITS * AX_ROWS);
    const float v0 = __ldg(v0p);

    const float4* __restrict__ gbase = (const float4*)x + brow0 * AX_RQ;
    const long long psps = n_rows * AX_T;

    // ---- prologue: fill all 4 ring stages (global chunks 0..3) ----
#pragma unroll
    for (int p = 0; p < AX_NSTAGE; ++p) {
        ax_issue_chunk(gbase, ax_smem + p * AX_STAGEQ, p, tid);
        ax_cp_commit();
    }

    const int rbase = tid * AX_STRIDE;

    float m = 0.0f, s = 0.0f;
    float dm = 0.0f, ds = 0.0f;
    long long my_row = 0;
    float* goutf = nullptr;

    for (int g = 0; g < AX_GCHUNK; ++g) {
        const int u  = g / AX_NCHUNK;
        const int ch = g - u * AX_NCHUNK;
        float4* stg = ax_smem + (g & (AX_NSTAGE - 1)) * AX_STAGEQ;

        ax_cp_wait<AX_NSTAGE - 1>();   // chunk g resident (in-order groups)
        __syncthreads();

        if (ch == 0) {                 // unit boundary: reset register state
            my_row = brow0 + (long long)u * AX_ROWS + tid;
            dm = __ldg(&decay_m[(int)(my_row % F)]);
            ds = __ldg(&decay_s[(int)(my_row % F)]);
            m = 0.0f; s = 0.0f;
            goutf = out + (brow0 + (long long)u * AX_ROWS) * AX_T;
        }

        // ---- sequential scan along T for this thread's row (in place) ----
#pragma unroll
        for (int t4 = 0; t4 < AX_CH4; ++t4) {
            float4 q = stg[rbase + t4];
            float4 o;
            m = fmaf(m, dm, q.x); s = fmaf(s, ds, q.x); o.x = (m - s) * v0;
            m = fmaf(m, dm, q.y); s = fmaf(s, ds, q.y); o.y = (m - s) * v0;
            m = fmaf(m, dm, q.z); s = fmaf(s, ds, q.z); o.z = (m - s) * v0;
            m = fmaf(m, dm, q.w); s = fmaf(s, ds, q.w); o.w = (m - s) * v0;
            stg[rbase + t4] = o;
        }
        __syncthreads();

        // ---- coalesced streaming store of chunk ----
#pragma unroll
        for (int i = 0; i < AX_CH4; ++i) {
            int idx = i * AX_THREADS + tid;
            int r = idx / AX_CH4;
            int c = idx - r * AX_CH4;
            float4 v = stg[r * AX_STRIDE + c];
            __stcs((float4*)(goutf + (long long)r * AX_T + (ch * AX_CH4 + c) * 4), v);
        }
        __syncthreads();               // stage fully read -> reusable

        // ---- refill this stage with global chunk g+4 (crosses units) ----
        if (g + AX_NSTAGE < AX_GCHUNK)
            ax_issue_chunk(gbase, stg, g + AX_NSTAGE, tid);
        ax_cp_commit();                // uniform group counting

        if (ch == AX_NCHUNK - 1) {     // unit done: emit final states
            out[psps + my_row]          = m;
            out[psps + n_rows + my_row] = s;
        }
    }
}

extern "C" void kernel_launch(void* const* d_in, const int* in_sizes, int n_in,
                              void* d_out, int out_size)
{
    const float* x   = (const float*)d_in[0];
    const float* dmv = (const float*)d_in[1];
    const float* dsv = (const float*)d_in[2];
    const float* v0p = (const float*)d_in[3];
    float* out = (float*)d_out;

    const int F = in_sizes[1];                       // 4096
    const long long total = (long long)in_sizes[0];  // B*F*T
    const long long n_rows = total / AX_T;           // 131072
    const int grid = (int)(n_rows / (AX_UNITS * AX_ROWS));   // 512

    const int smem_bytes = AX_NSTAGE * AX_STAGEQ * (int)sizeof(float4); // 45056

    static bool attr_set = false;
    if (!attr_set) {
        cudaFuncSetAttribute(axon_cring_kernel,
                             cudaFuncAttributeMaxDynamicSharedMemorySize,
                             smem_bytes);
        attr_set = true;
    }

    axon_cring_kernel<<<grid, AX_THREADS, smem_bytes>>>(
        x, dmv, dsv, v0p, out, F, n_rows);
}

// round 14
// speedup vs baseline: 1.1778x; 1.1778x over previous
#include <cuda_runtime.h>

// axon_layer: dual-exponential PSP scan.
//   m_t = m_{t-1}*dm + x_t ; s_t = s_{t-1}*ds + x_t ; psp_t = (m_t - s_t)*v0
//
// R9 machinery with reduced phase overhead: 3-stage cp.async load ring plus a
// DEDICATED store buffer, so the store (smem->gmem) and the refill
// (gmem->smem) issue in the SAME phase after a single barrier. 2 barriers per
// chunk instead of 3. smem = 45 KB -> 5 blocks/SM, grid 2048, chunk = 10
// float4/row (160 B), stride 11 (conflict-free). Bit-exact sequential scan.
//
// Inputs: [0] input_spikes f32 [B,F,T]  [1] decay_m f32 [F]
//         [2] decay_s f32 [F]           [3] v_0 f32 scalar
// Output: psps [B,F,T] then m_T [B,F] then s_T [B,F].

#define AX_THREADS 64
#define AX_ROWS    64
#define AX_T       400
#define AX_CH4     10            // float4 per chunk (160 B/row)
#define AX_STRIDE  11            // padded smem row stride (odd -> no LDS conflicts)
#define AX_NCHUNK  10
#define AX_NL      3             // load ring stages
#define AX_RQ      (AX_T / 4)    // 100 float4 per row
#define AX_STAGEQ  (AX_ROWS * AX_STRIDE)   // 704 quads = 11264 B per stage

__device__ __forceinline__ void ax_cp_async16(void* smem_dst, const void* gmem_src) {
    unsigned saddr = (unsigned)__cvta_generic_to_shared(smem_dst);
    asm volatile("cp.async.cg.shared.global [%0], [%1], 16;\n"
                 :: "r"(saddr), "l"(gmem_src));
}
__device__ __forceinline__ void ax_cp_commit() {
    asm volatile("cp.async.commit_group;\n");
}
template <int N>
__device__ __forceinline__ void ax_cp_wait() {
    asm volatile("cp.async.wait_group %0;\n" :: "n"(N));
}

extern __shared__ float4 ax_smem[];   // (AX_NL + 1) * AX_STAGEQ = 45056 B

// Stage one chunk (64 rows x 10 quads) into a load stage (strip-mined,
// gmem-coalesced). Caller commits the group.
__device__ __forceinline__ void ax_issue_chunk(const float4* __restrict__ gin,
                                               float4* __restrict__ stg,
                                               int ch, int tid)
{
#pragma unroll
    for (int i = 0; i < AX_CH4; ++i) {
        int idx = i * AX_THREADS + tid;          // 0..639 linear over tile
        int r = idx / AX_CH4;
        int c = idx - r * AX_CH4;
        ax_cp_async16(&stg[r * AX_STRIDE + c],
                      &gin[(long long)r * AX_RQ + ch * AX_CH4 + c]);
    }
}

__global__ void __launch_bounds__(AX_THREADS)
axon_r9m_kernel(const float* __restrict__ x,
                const float* __restrict__ decay_m,
                const float* __restrict__ decay_s,
                const float* __restrict__ v0p,
                float* __restrict__ out,
                int F, long long n_rows)
{
    const int tid = threadIdx.x;
    const long long row0 = (long long)blockIdx.x * AX_ROWS;
    const long long my_row = row0 + tid;

    const float dm = __ldg(&decay_m[(int)(my_row % F)]);
    const float ds = __ldg(&decay_s[(int)(my_row % F)]);
    const float v0 = __ldg(v0p);

    float m = 0.0f, s = 0.0f;

    const float4* __restrict__ gin   = (const float4*)x + row0 * AX_RQ;
    float*        __restrict__ goutf = out + row0 * AX_T;

    float4* S = ax_smem + AX_NL * AX_STAGEQ;   // dedicated store buffer

    // ---- prologue: fill the 3 load stages (chunks 0..2 in flight) ----
#pragma unroll
    for (int p = 0; p < AX_NL; ++p) {
        ax_issue_chunk(gin, ax_smem + p * AX_STAGEQ, p, tid);
        ax_cp_commit();
    }

    const int rbase = tid * AX_STRIDE;
    int lstage = 0;

    for (int ch = 0; ch < AX_NCHUNK; ++ch) {
        float4* L = ax_smem + lstage * AX_STAGEQ;

        ax_cp_wait<AX_NL - 1>();   // chunk ch resident (in-order groups)
        __syncthreads();           // also orders prev LDS-of-S before STS-of-S

        // ---- scan this thread's row: read L, write result to S ----
#pragma unroll
        for (int t4 = 0; t4 < AX_CH4; ++t4) {
            float4 q = L[rbase + t4];
            float4 o;
            m = fmaf(m, dm, q.x); s = fmaf(s, ds, q.x); o.x = (m - s) * v0;
            m = fmaf(m, dm, q.y); s = fmaf(s, ds, q.y); o.y = (m - s) * v0;
            m = fmaf(m, dm, q.z); s = fmaf(s, ds, q.z); o.z = (m - s) * v0;
            m = fmaf(m, dm, q.w); s = fmaf(s, ds, q.w); o.w = (m - s) * v0;
            S[rbase + t4] = o;
        }
        __syncthreads();           // S complete; L reads complete

        // ---- merged phase: coalesced store of S AND refill of L ----
#pragma unroll
        for (int i = 0; i < AX_CH4; ++i) {
            int idx = i * AX_THREADS + tid;
            int r = idx / AX_CH4;
            int c = idx - r * AX_CH4;
            float4 v = S[r * AX_STRIDE + c];
            __stcs((float4*)(goutf + (long long)r * AX_T + (ch * AX_CH4 + c) * 4), v);
        }
        if (ch + AX_NL < AX_NCHUNK)
            ax_issue_chunk(gin, L, ch + AX_NL, tid);
        ax_cp_commit();            // always commit: uniform group counting

        lstage = (lstage == AX_NL - 1) ? 0 : lstage + 1;
    }

    // ---- final states ----
    const long long psps = n_rows * AX_T;
    out[psps + my_row]          = m;
    out[psps + n_rows + my_row] = s;
}

extern "C" void kernel_launch(void* const* d_in, const int* in_sizes, int n_in,
                              void* d_out, int out_size)
{
    const float* x   = (const float*)d_in[0];
    const float* dmv = (const float*)d_in[1];
    const float* dsv = (const float*)d_in[2];
    const float* v0p = (const float*)d_in[3];
    float* out = (float*)d_out;

    const int F = in_sizes[1];                       // 4096
    const long long total = (long long)in_sizes[0];  // B*F*T
    const long long n_rows = total / AX_T;           // 131072
    const int grid = (int)(n_rows / AX_ROWS);        // 2048

    const int smem_bytes = (AX_NL + 1) * AX_STAGEQ * (int)sizeof(float4); // 45056

    static bool attr_set = false;
    if (!attr_set) {
        cudaFuncSetAttribute(axon_r9m_kernel,
                             cudaFuncAttributeMaxDynamicSharedMemorySize,
                             smem_bytes);
        attr_set = true;
    }

    axon_r9m_kernel<<<grid, AX_THREADS, smem_bytes>>>(
        x, dmv, dsv, v0p, out, F, n_rows);
}

// round 15
// speedup vs baseline: 1.1934x; 1.0133x over previous
#include <cuda_runtime.h>
#include <cuda.h>
#include <cstdint>

// axon_layer: dual-exponential PSP scan.
//   m_t = m_{t-1}*dm + x_t ; s_t = s_{t-1}*ds + x_t ; psp_t = (m_t - s_t)*v0
//
// R14 skeleton with TMA 2D tensor-tile movers: one cp.async.bulk.tensor.2d
// per 64-row x 160B stage (load AND store) instead of 640 LDGSTS / 160 STG
// per chunk -> warp LSU does only the LDS/STS of the scan itself. 3 load
// stages + 1 store stage (41 KB smem, 5 blocks/SM), grid 2048, 2 barriers
// per chunk. Tensor maps built via cudaGetDriverEntryPoint (no -lcuda).
//
// Inputs: [0] input_spikes f32 [B,F,T]  [1] decay_m f32 [F]
//         [2] decay_s f32 [F]           [3] v_0 f32 scalar
// Output: psps [B,F,T] then m_T [B,F] then s_T [B,F].

#define AX_THREADS 64
#define AX_ROWS    64
#define AX_T       400
#define AX_CHF     40                      // floats per chunk per row (160 B)
#define AX_CH4     (AX_CHF / 4)            // 10 quads
#define AX_NCHUNK  10
#define AX_NL      3                       // load ring stages
#define AX_STAGEB  (AX_ROWS * AX_CHF * 4)  // 10240 B per stage
#define SM_S       (AX_NL * AX_STAGEB)     // store stage offset  (30720)
#define SM_MBAR    (SM_S + AX_STAGEB)      // mbarriers offset    (40960)
#define SM_TOTAL   (SM_MBAR + 64)          // 41024 B

__device__ __forceinline__ uint32_t ax_s32(const void* p) {
    return (uint32_t)__cvta_generic_to_shared(p);
}
__device__ __forceinline__ void ax_mbar_init(uint32_t mbar, uint32_t cnt) {
    asm volatile("mbarrier.init.shared.b64 [%0], %1;" :: "r"(mbar), "r"(cnt) : "memory");
}
__device__ __forceinline__ void ax_expect_tx(uint32_t mbar, uint32_t bytes) {
    asm volatile("mbarrier.arrive.expect_tx.shared.b64 _, [%0], %1;"
                 :: "r"(mbar), "r"(bytes) : "memory");
}
__device__ __forceinline__ void ax_wait_parity(uint32_t mbar, uint32_t parity) {
    uint32_t done;
    asm volatile(
        "{\n\t.reg .pred p;\n\t"
        "mbarrier.try_wait.parity.acquire.cta.shared::cta.b64 p, [%1], %2;\n\t"
        "selp.b32 %0, 1, 0, p;\n\t}"
        : "=r"(done) : "r"(mbar), "r"(parity) : "memory");
    if (!done) {
        asm volatile(
            "{\n\t.reg .pred P1;\n\t"
            "WL_%=:\n\t"
            "mbarrier.try_wait.parity.acquire.cta.shared::cta.b64 P1, [%0], %1, 0x989680;\n\t"
            "@P1 bra.uni WD_%=;\n\t"
            "bra.uni WL_%=;\n\t"
            "WD_%=:\n\t}"
            :: "r"(mbar), "r"(parity) : "memory");
    }
}
__device__ __forceinline__ void ax_tma_load2d(uint32_t sdst, const CUtensorMap* map,
                                              int x, int y, uint32_t mbar) {
    asm volatile(
        "cp.async.bulk.tensor.2d.shared::cta.global.tile.mbarrier::complete_tx::bytes "
        "[%0], [%1, {%2, %3}], [%4];"
        :: "r"(sdst), "l"(map), "r"(x), "r"(y), "r"(mbar) : "memory");
}
__device__ __forceinline__ void ax_tma_store2d(const CUtensorMap* map,
                                               int x, int y, uint32_t ssrc) {
    asm volatile(
        "cp.async.bulk.tensor.2d.global.shared::cta.tile.bulk_group "
        "[%0, {%1, %2}], [%3];"
        :: "l"(map), "r"(x), "r"(y), "r"(ssrc) : "memory");
}
__device__ __forceinline__ void ax_bulk_commit() {
    asm volatile("cp.async.bulk.commit_group;" ::: "memory");
}
__device__ __forceinline__ void ax_bulk_wait_read0() {
    asm volatile("cp.async.bulk.wait_group.read 0;" ::: "memory");
}
__device__ __forceinline__ void ax_bulk_wait_all() {
    asm volatile("cp.async.bulk.wait_group 0;" ::: "memory");
}

extern __shared__ char ax_smem[];

__global__ void __launch_bounds__(AX_THREADS)
axon_tma_kernel(const __grid_constant__ CUtensorMap in_map,
                const __grid_constant__ CUtensorMap out_map,
                const float* __restrict__ decay_m,
                const float* __restrict__ decay_s,
                const float* __restrict__ v0p,
                float* __restrict__ out,
                int F, long long n_rows)
{
    const int tid = threadIdx.x;
    const long long row0 = (long long)blockIdx.x * AX_ROWS;
    const long long my_row = row0 + tid;

    const float dm = __ldg(&decay_m[(int)(my_row % F)]);
    const float ds = __ldg(&decay_s[(int)(my_row % F)]);
    const float v0 = __ldg(v0p);

    const uint32_t sbase = ax_s32(ax_smem);
    const uint32_t mb0 = sbase + SM_MBAR;

    if (tid == 0) {
#pragma unroll
        for (int p = 0; p < AX_NL; ++p) ax_mbar_init(mb0 + p * 8, 1);
        asm volatile("fence.mbarrier_init.release.cluster;" ::: "memory");
    }
    __syncthreads();

    // ---- prologue: TMA-load chunks 0..2 into the 3 load stages ----
    if (tid == 0) {
#pragma unroll
        for (int p = 0; p < AX_NL; ++p) {
            ax_expect_tx(mb0 + p * 8, AX_STAGEB);
            ax_tma_load2d(sbase + p * AX_STAGEB, &in_map,
                          p * AX_CHF, (int)row0, mb0 + p * 8);
        }
    }

    float m = 0.0f, s = 0.0f;
    float4* S4 = (float4*)(ax_smem + SM_S) + tid * AX_CH4;

    for (int ch = 0; ch < AX_NCHUNK; ++ch) {
        const int st = ch % AX_NL;
        const uint32_t parity = (uint32_t)((ch / AX_NL) & 1);

        ax_wait_parity(mb0 + st * 8, parity);   // load stage st has chunk ch
        if (tid == 0) ax_bulk_wait_read0();     // previous store drained S
        __syncthreads();

        const float4* L4 = (const float4*)(ax_smem + st * AX_STAGEB) + tid * AX_CH4;

        // ---- sequential scan of this thread's row segment: L -> S ----
#pragma unroll
        for (int q = 0; q < AX_CH4; ++q) {
            float4 v = L4[q];
            float4 o;
            m = fmaf(m, dm, v.x); s = fmaf(s, ds, v.x); o.x = (m - s) * v0;
            m = fmaf(m, dm, v.y); s = fmaf(s, ds, v.y); o.y = (m - s) * v0;
            m = fmaf(m, dm, v.z); s = fmaf(s, ds, v.z); o.z = (m - s) * v0;
            m = fmaf(m, dm, v.w); s = fmaf(s, ds, v.w); o.w = (m - s) * v0;
            S4[q] = o;
        }
        asm volatile("fence.proxy.async.shared::cta;" ::: "memory");
        __syncthreads();

        // ---- one TMA store of S + one TMA refill of stage st ----
        if (tid == 0) {
            ax_tma_store2d(&out_map, ch * AX_CHF, (int)row0, sbase + SM_S);
            ax_bulk_commit();
            if (ch + AX_NL < AX_NCHUNK) {
                ax_expect_tx(mb0 + st * 8, AX_STAGEB);
                ax_tma_load2d(sbase + st * AX_STAGEB, &in_map,
                              (ch + AX_NL) * AX_CHF, (int)row0, mb0 + st * 8);
            }
        }
    }

    // ---- final states ----
    const long long psps = n_rows * AX_T;
    out[psps + my_row]          = m;
    out[psps + n_rows + my_row] = s;

    if (tid == 0) ax_bulk_wait_all();   // drain outstanding TMA stores
}

extern "C" void kernel_launch(void* const* d_in, const int* in_sizes, int n_in,
                              void* d_out, int out_size)
{
    const float* x   = (const float*)d_in[0];
    const float* dmv = (const float*)d_in[1];
    const float* dsv = (const float*)d_in[2];
    const float* v0p = (const float*)d_in[3];
    float* out = (float*)d_out;

    const int F = in_sizes[1];                       // 4096
    const long long total = (long long)in_sizes[0];  // B*F*T
    const long long n_rows = total / AX_T;           // 131072
    const int grid = (int)(n_rows / AX_ROWS);        // 2048

    // --- tensor maps (driver entry point via runtime; no -lcuda link) ---
    typedef CUresult (*EncodeFn)(CUtensorMap*, CUtensorMapDataType, cuuint32_t,
                                 void*, const cuuint64_t*, const cuuint64_t*,
                                 const cuuint32_t*, const cuuint32_t*,
                                 CUtensorMapInterleave, CUtensorMapSwizzle,
                                 CUtensorMapL2promotion, CUtensorMapFloatOOBfill);
    static EncodeFn enc = nullptr;
    if (!enc) {
        cudaDriverEntryPointQueryResult qr;
        void* fp = nullptr;
        cudaGetDriverEntryPoint("cuTensorMapEncodeTiled", &fp,
                                cudaEnableDefault, &qr);
        enc = (EncodeFn)fp;
    }

    cuuint64_t dims[2]    = { (cuuint64_t)AX_T, (cuuint64_t)n_rows };
    cuuint64_t strides[1] = { (cuuint64_t)AX_T * sizeof(float) };   // 1600 B
    cuuint32_t box[2]     = { AX_CHF, AX_ROWS };                    // 40 x 64
    cuuint32_t es[2]      = { 1, 1 };

    CUtensorMap in_map, out_map;
    enc(&in_map, CU_TENSOR_MAP_DATA_TYPE_FLOAT32, 2, (void*)x,
        dims, strides, box, es,
        CU_TENSOR_MAP_INTERLEAVE_NONE, CU_TENSOR_MAP_SWIZZLE_NONE,
        CU_TENSOR_MAP_L2_PROMOTION_L2_128B, CU_TENSOR_MAP_FLOAT_OOB_FILL_NONE);
    enc(&out_map, CU_TENSOR_MAP_DATA_TYPE_FLOAT32, 2, (void*)out,
        dims, strides, box, es,
        CU_TENSOR_MAP_INTERLEAVE_NONE, CU_TENSOR_MAP_SWIZZLE_NONE,
        CU_TENSOR_MAP_L2_PROMOTION_L2_128B, CU_TENSOR_MAP_FLOAT_OOB_FILL_NONE);

    static bool attr_set = false;
    if (!attr_set) {
        cudaFuncSetAttribute(axon_tma_kernel,
                             cudaFuncAttributeMaxDynamicSharedMemorySize,
                             SM_TOTAL);
        attr_set = true;
    }

    axon_tma_kernel<<<grid, AX_THREADS, SM_TOTAL>>>(
        in_map, out_map, dmv, dsv, v0p, out, F, n_rows);
}